// round 14
// baseline (speedup 1.0000x reference)
#include <cuda_runtime.h>
#include <cuda_fp16.h>
#include <math.h>

// Problem constants
#define BB 16
#define HH 384
#define WW 512
#define CC 3
#define HW (HH * WW)
#define NPIX (BB * HW)
#define NQUAD (NPIX / 4)

// Gather tiling: warp covers 16 wide x 4 tall; block = 8 warps = 16 x 32
#define TILE_W 16
#define TILE_H 32

// fp16-padded source image: [B,H,W] x (half c0,c1,c2,pad) = 8B/pixel, 25.2MB
__device__ uint2 g_pad[NPIX];

__device__ __forceinline__ unsigned pack2(float a, float b) {
    unsigned lo = (unsigned)__half_as_ushort(__float2half_rn(a));
    unsigned hi = (unsigned)__half_as_ushort(__float2half_rn(b));
    return lo | (hi << 16);
}
__device__ __forceinline__ uint2 pack_px(float c0, float c1, float c2) {
    uint2 r;
    r.x = pack2(c0, c1);
    r.y = pack2(c2, 0.0f);
    return r;
}
__device__ __forceinline__ float2 unpack2(unsigned w) {
    __half2 h = *reinterpret_cast<const __half2*>(&w);
    return __half22float2(h);
}

// Compute per-batch projection matrix N[9] + T[3] from pose/K (inline, ~150 flops)
__device__ __forceinline__ void compute_pose(
    const float* __restrict__ pose, const float* __restrict__ K, int b,
    float* N, float* T)
{
    float tx = pose[b * 6 + 0] * 0.01f;
    float ty = pose[b * 6 + 1] * 0.01f;
    float tz = pose[b * 6 + 2] * 0.01f;
    float rx = pose[b * 6 + 3] * 0.001f;
    float ry = pose[b * 6 + 4] * 0.001f;
    float rz = pose[b * 6 + 5] * 0.001f;

    float cx = cosf(rx), sx = sinf(rx);
    float cy = cosf(ry), sy = sinf(ry);
    float cz = cosf(rz), sz = sinf(rz);

    // R = Rz @ Ry @ Rx
    float Rzy[9];
    Rzy[0] = cz * cy;  Rzy[1] = -sz;  Rzy[2] = cz * sy;
    Rzy[3] = sz * cy;  Rzy[4] = cz;   Rzy[5] = sz * sy;
    Rzy[6] = -sy;      Rzy[7] = 0.f;  Rzy[8] = cy;
    float R[9];
    R[0] = Rzy[0];
    R[1] = Rzy[1] * cx + Rzy[2] * sx;
    R[2] = -Rzy[1] * sx + Rzy[2] * cx;
    R[3] = Rzy[3];
    R[4] = Rzy[4] * cx + Rzy[5] * sx;
    R[5] = -Rzy[4] * sx + Rzy[5] * cx;
    R[6] = Rzy[6];
    R[7] = Rzy[7] * cx + Rzy[8] * sx;
    R[8] = -Rzy[7] * sx + Rzy[8] * cx;

    float k00 = K[0], k01 = K[1], k02 = K[2];
    float k10 = K[3], k11 = K[4], k12 = K[5];
    float k20 = K[6], k21 = K[7], k22 = K[8];

    float c00 = k11 * k22 - k12 * k21;
    float c01 = k12 * k20 - k10 * k22;
    float c02 = k10 * k21 - k11 * k20;
    float det = k00 * c00 + k01 * c01 + k02 * c02;
    float id = 1.0f / det;
    float Ki[9];
    Ki[0] = c00 * id;
    Ki[1] = (k02 * k21 - k01 * k22) * id;
    Ki[2] = (k01 * k12 - k02 * k11) * id;
    Ki[3] = c01 * id;
    Ki[4] = (k00 * k22 - k02 * k20) * id;
    Ki[5] = (k02 * k10 - k00 * k12) * id;
    Ki[6] = c02 * id;
    Ki[7] = (k01 * k20 - k00 * k21) * id;
    Ki[8] = (k00 * k11 - k01 * k10) * id;

    float M33[9];
    #pragma unroll
    for (int i = 0; i < 3; i++) {
        float a0 = (i == 0) ? k00 : (i == 1) ? k10 : k20;
        float a1 = (i == 0) ? k01 : (i == 1) ? k11 : k21;
        float a2 = (i == 0) ? k02 : (i == 1) ? k12 : k22;
        #pragma unroll
        for (int j = 0; j < 3; j++)
            M33[i * 3 + j] = a0 * R[j] + a1 * R[3 + j] + a2 * R[6 + j];
        T[i] = a0 * tx + a1 * ty + a2 * tz;
    }

    #pragma unroll
    for (int i = 0; i < 3; i++)
        #pragma unroll
        for (int j = 0; j < 3; j++)
            N[i * 3 + j] = M33[i * 3 + 0] * Ki[j]
                         + M33[i * 3 + 1] * Ki[3 + j]
                         + M33[i * 3 + 2] * Ki[6 + j];
}

// ---------------------------------------------------------------------------
// Kernel 1: pad source to fp16 layout (1 quad/thread — measured best shape).
// __ldcs on src (never reused); explicit PDL trigger after stores.
// ---------------------------------------------------------------------------
__global__ void __launch_bounds__(256) pad_kernel(const float* __restrict__ src)
{
    int t = blockIdx.x * blockDim.x + threadIdx.x;

    if (t < NQUAD) {
        const float4* s = (const float4*)src;
        float4 f0 = __ldcs(&s[3 * t + 0]);
        float4 f1 = __ldcs(&s[3 * t + 1]);
        float4 f2 = __ldcs(&s[3 * t + 2]);
        uint2 p0 = pack_px(f0.x, f0.y, f0.z);
        uint2 p1 = pack_px(f0.w, f1.x, f1.y);
        uint2 p2 = pack_px(f1.z, f1.w, f2.x);
        uint2 p3 = pack_px(f2.y, f2.z, f2.w);
        uint4* dst = (uint4*)&g_pad[4 * t];
        dst[0] = make_uint4(p0.x, p0.y, p1.x, p1.y);
        dst[1] = make_uint4(p2.x, p2.y, p3.x, p3.y);
    }

#if __CUDA_ARCH__ >= 900
    cudaTriggerProgrammaticLaunchCompletion();
#endif
}

// ---------------------------------------------------------------------------
// Kernel 2: warp + bilinear gather. 2 px/thread, 2-D warp tiles (16x4).
// Pose matrix computed inline per-thread (no global dependency pre-sync).
// PDL: everything except the tap loads runs before the grid sync.
// ---------------------------------------------------------------------------
__global__ void __launch_bounds__(256) warp_kernel(
    const float* __restrict__ depth,
    const float* __restrict__ pose,
    const float* __restrict__ K,
    float* __restrict__ out)
{
    int lane = threadIdx.x & 31;
    int warp = threadIdx.x >> 5;
    int b = blockIdx.z;

    int row_in_warp = lane >> 3;        // 0..3
    int col8 = lane & 7;                // 0..7
    int v = blockIdx.y * TILE_H + warp * 4 + row_in_warp;
    int u0 = blockIdx.x * TILE_W + col8 * 2;

    int pix0 = b * HW + v * WW + u0;

    // Issue depth load first (longest latency), pose math overlaps it
    float2 dv = __ldg((const float2*)&depth[pix0]);

    float N[9], T[3];
    compute_pose(pose, K, b, N, T);

    float vf = (float)v;
    float rx_ = fmaf(N[1], vf, N[2]);
    float ry_ = fmaf(N[4], vf, N[5]);
    float rz_ = fmaf(N[7], vf, N[8]);

    const uint2* pb_ = &g_pad[(size_t)b * HW];

    int ia0[2], ia1[2], ib0[2], ib1[2];
    float wA[2], wB[2], wC[2], wD[2];

    #pragma unroll
    for (int j = 0; j < 2; j++) {
        float d = (j == 0) ? dv.x : dv.y;
        float uf = (float)(u0 + j);
        float px = fmaf(d, fmaf(N[0], uf, rx_), T[0]);
        float py = fmaf(d, fmaf(N[3], uf, ry_), T[1]);
        float pz = fmaf(d, fmaf(N[6], uf, rz_), T[2]);
        float inv_z = 1.0f / (pz + 1e-10f);
        float xs = px * inv_z;
        float ys = py * inv_z;

        float x0f = floorf(xs), y0f = floorf(ys);
        float fx = xs - x0f, fy = ys - y0f;
        float gx = 1.0f - fx, gy = 1.0f - fy;
        wA[j] = gx * gy;
        wB[j] = gx * fy;
        wC[j] = fx * gy;
        wD[j] = fx * fy;

        int x0 = (int)fminf(fmaxf(x0f, 0.0f), (float)(WW - 1));
        int x1 = (int)fminf(fmaxf(x0f + 1.0f, 0.0f), (float)(WW - 1));
        int y0 = (int)fminf(fmaxf(y0f, 0.0f), (float)(HH - 1));
        int y1 = (int)fminf(fmaxf(y0f + 1.0f, 0.0f), (float)(HH - 1));

        ia0[j] = y0 * WW + x0;
        ia1[j] = y0 * WW + x1;
        ib0[j] = y1 * WW + x0;
        ib1[j] = y1 * WW + x1;
    }

#if __CUDA_ARCH__ >= 900
    cudaGridDependencySynchronize();    // wait for pad before touching g_pad
#endif

    // All 8 tap loads back-to-back for MLP
    uint2 A0 = __ldg(&pb_[ia0[0]]);
    uint2 C0 = __ldg(&pb_[ia1[0]]);
    uint2 B0 = __ldg(&pb_[ib0[0]]);
    uint2 D0 = __ldg(&pb_[ib1[0]]);
    uint2 A1 = __ldg(&pb_[ia0[1]]);
    uint2 C1 = __ldg(&pb_[ia1[1]]);
    uint2 B1 = __ldg(&pb_[ib0[1]]);
    uint2 D1 = __ldg(&pb_[ib1[1]]);

    float o[6];
    {
        float2 a01 = unpack2(A0.x), a2 = unpack2(A0.y);
        float2 b01 = unpack2(B0.x), b2 = unpack2(B0.y);
        float2 c01 = unpack2(C0.x), c2 = unpack2(C0.y);
        float2 d01 = unpack2(D0.x), d2 = unpack2(D0.y);
        o[0] = fmaf(wA[0], a01.x, fmaf(wB[0], b01.x, fmaf(wC[0], c01.x, wD[0] * d01.x)));
        o[1] = fmaf(wA[0], a01.y, fmaf(wB[0], b01.y, fmaf(wC[0], c01.y, wD[0] * d01.y)));
        o[2] = fmaf(wA[0], a2.x,  fmaf(wB[0], b2.x,  fmaf(wC[0], c2.x,  wD[0] * d2.x)));
    }
    {
        float2 a01 = unpack2(A1.x), a2 = unpack2(A1.y);
        float2 b01 = unpack2(B1.x), b2 = unpack2(B1.y);
        float2 c01 = unpack2(C1.x), c2 = unpack2(C1.y);
        float2 d01 = unpack2(D1.x), d2 = unpack2(D1.y);
        o[3] = fmaf(wA[1], a01.x, fmaf(wB[1], b01.x, fmaf(wC[1], c01.x, wD[1] * d01.x)));
        o[4] = fmaf(wA[1], a01.y, fmaf(wB[1], b01.y, fmaf(wC[1], c01.y, wD[1] * d01.y)));
        o[5] = fmaf(wA[1], a2.x,  fmaf(wB[1], b2.x,  fmaf(wC[1], c2.x,  wD[1] * d2.x)));
    }

    float2* ov = (float2*)(out + (size_t)pix0 * CC);
    ov[0] = make_float2(o[0], o[1]);
    ov[1] = make_float2(o[2], o[3]);
    ov[2] = make_float2(o[4], o[5]);
}

extern "C" void kernel_launch(void* const* d_in, const int* in_sizes, int n_in,
                              void* d_out, int out_size) {
    const float* src   = (const float*)d_in[0];   // [B,H,W,C]
    const float* depth = (const float*)d_in[1];   // [B,H,W]
    const float* pose  = (const float*)d_in[2];   // [B,6]
    const float* K     = (const float*)d_in[3];   // [3,3]
    float* out = (float*)d_out;

    const int threads = 256;

    int pad_blocks = (NQUAD + threads - 1) / threads;      // 3072
    pad_kernel<<<pad_blocks, threads>>>(src);

    // Gather with Programmatic Dependent Launch on the pad kernel
    cudaLaunchConfig_t cfg = {};
    cfg.gridDim = dim3(WW / TILE_W, HH / TILE_H, BB);      // 32 x 12 x 16
    cfg.blockDim = dim3(threads, 1, 1);
    cfg.dynamicSmemBytes = 0;
    cfg.stream = 0;
    cudaLaunchAttribute attrs[1];
    attrs[0].id = cudaLaunchAttributeProgrammaticStreamSerialization;
    attrs[0].val.programmaticStreamSerializationAllowed = 1;
    cfg.attrs = attrs;
    cfg.numAttrs = 1;
    cudaLaunchKernelEx(&cfg, warp_kernel, depth, pose, K, out);
}

// round 15
// speedup vs baseline: 1.1963x; 1.1963x over previous
#include <cuda_runtime.h>
#include <cuda_fp16.h>
#include <math.h>

// Problem constants
#define BB 16
#define HH 384
#define WW 512
#define CC 3
#define HW (HH * WW)
#define NPIX (BB * HW)
#define NQUAD (NPIX / 4)

// Gather tiling: warp covers 16 wide x 4 tall; block = 8 warps = 16 x 32
#define TILE_W 16
#define TILE_H 32

// Per-batch precomputed transform: p = d * (N @ [u,v,1]) + T
__device__ float g_M[BB][12];
// fp16-padded source image: [B,H,W] x (half c0,c1,c2,pad) = 8B/pixel, 25.2MB
__device__ uint2 g_pad[NPIX];

__device__ __forceinline__ unsigned pack2(float a, float b) {
    unsigned lo = (unsigned)__half_as_ushort(__float2half_rn(a));
    unsigned hi = (unsigned)__half_as_ushort(__float2half_rn(b));
    return lo | (hi << 16);
}
__device__ __forceinline__ uint2 pack_px(float c0, float c1, float c2) {
    uint2 r;
    r.x = pack2(c0, c1);
    r.y = pack2(c2, 0.0f);
    return r;
}
__device__ __forceinline__ float2 unpack2(unsigned w) {
    __half2 h = *reinterpret_cast<const __half2*>(&w);
    return __half22float2(h);
}

// ---------------------------------------------------------------------------
// Kernel 1: pad source to fp16 layout (1 quad/thread — measured best shape);
// block 0 also computes pose matrices into g_M. PDL trigger after all stores.
// ---------------------------------------------------------------------------
__global__ void __launch_bounds__(256) pad_pose_kernel(
    const float* __restrict__ src,
    const float* __restrict__ pose,
    const float* __restrict__ K)
{
    int t = blockIdx.x * blockDim.x + threadIdx.x;

    if (t < NQUAD) {
        const float4* s = (const float4*)src;
        float4 f0 = __ldcs(&s[3 * t + 0]);
        float4 f1 = __ldcs(&s[3 * t + 1]);
        float4 f2 = __ldcs(&s[3 * t + 2]);
        uint2 p0 = pack_px(f0.x, f0.y, f0.z);
        uint2 p1 = pack_px(f0.w, f1.x, f1.y);
        uint2 p2 = pack_px(f1.z, f1.w, f2.x);
        uint2 p3 = pack_px(f2.y, f2.z, f2.w);
        uint4* dst = (uint4*)&g_pad[4 * t];
        dst[0] = make_uint4(p0.x, p0.y, p1.x, p1.y);
        dst[1] = make_uint4(p2.x, p2.y, p3.x, p3.y);
    }

    if (blockIdx.x == 0 && threadIdx.x < BB) {
        int b = threadIdx.x;

        float tx = pose[b * 6 + 0] * 0.01f;
        float ty = pose[b * 6 + 1] * 0.01f;
        float tz = pose[b * 6 + 2] * 0.01f;
        float rx = pose[b * 6 + 3] * 0.001f;
        float ry = pose[b * 6 + 4] * 0.001f;
        float rz = pose[b * 6 + 5] * 0.001f;

        float cx = cosf(rx), sx = sinf(rx);
        float cy = cosf(ry), sy = sinf(ry);
        float cz = cosf(rz), sz = sinf(rz);

        // R = Rz @ Ry @ Rx
        float Rzy[9];
        Rzy[0] = cz * cy;  Rzy[1] = -sz;  Rzy[2] = cz * sy;
        Rzy[3] = sz * cy;  Rzy[4] = cz;   Rzy[5] = sz * sy;
        Rzy[6] = -sy;      Rzy[7] = 0.f;  Rzy[8] = cy;
        float R[9];
        R[0] = Rzy[0];
        R[1] = Rzy[1] * cx + Rzy[2] * sx;
        R[2] = -Rzy[1] * sx + Rzy[2] * cx;
        R[3] = Rzy[3];
        R[4] = Rzy[4] * cx + Rzy[5] * sx;
        R[5] = -Rzy[4] * sx + Rzy[5] * cx;
        R[6] = Rzy[6];
        R[7] = Rzy[7] * cx + Rzy[8] * sx;
        R[8] = -Rzy[7] * sx + Rzy[8] * cx;

        float k00 = K[0], k01 = K[1], k02 = K[2];
        float k10 = K[3], k11 = K[4], k12 = K[5];
        float k20 = K[6], k21 = K[7], k22 = K[8];

        float c00 = k11 * k22 - k12 * k21;
        float c01 = k12 * k20 - k10 * k22;
        float c02 = k10 * k21 - k11 * k20;
        float det = k00 * c00 + k01 * c01 + k02 * c02;
        float id = 1.0f / det;
        float Ki[9];
        Ki[0] = c00 * id;
        Ki[1] = (k02 * k21 - k01 * k22) * id;
        Ki[2] = (k01 * k12 - k02 * k11) * id;
        Ki[3] = c01 * id;
        Ki[4] = (k00 * k22 - k02 * k20) * id;
        Ki[5] = (k02 * k10 - k00 * k12) * id;
        Ki[6] = c02 * id;
        Ki[7] = (k01 * k20 - k00 * k21) * id;
        Ki[8] = (k00 * k11 - k01 * k10) * id;

        float M33[9], Mt[3];
        #pragma unroll
        for (int i = 0; i < 3; i++) {
            float a0 = (i == 0) ? k00 : (i == 1) ? k10 : k20;
            float a1 = (i == 0) ? k01 : (i == 1) ? k11 : k21;
            float a2 = (i == 0) ? k02 : (i == 1) ? k12 : k22;
            #pragma unroll
            for (int j = 0; j < 3; j++)
                M33[i * 3 + j] = a0 * R[j] + a1 * R[3 + j] + a2 * R[6 + j];
            Mt[i] = a0 * tx + a1 * ty + a2 * tz;
        }

        #pragma unroll
        for (int i = 0; i < 3; i++) {
            #pragma unroll
            for (int j = 0; j < 3; j++) {
                g_M[b][i * 3 + j] = M33[i * 3 + 0] * Ki[j]
                                  + M33[i * 3 + 1] * Ki[3 + j]
                                  + M33[i * 3 + 2] * Ki[6 + j];
            }
            g_M[b][9 + i] = Mt[i];
        }
    }

#if __CUDA_ARCH__ >= 900
    cudaTriggerProgrammaticLaunchCompletion();
#endif
}

// ---------------------------------------------------------------------------
// Kernel 2: warp + bilinear gather. 2 px/thread, 2-D warp tiles (16x4).
// PDL: only the depth load (input-only) runs before the grid sync;
// g_M read + projection + taps after (g_M is pad-grid-written).
// ---------------------------------------------------------------------------
__global__ void __launch_bounds__(256) warp_kernel(
    const float* __restrict__ depth,
    float* __restrict__ out)
{
    int lane = threadIdx.x & 31;
    int warp = threadIdx.x >> 5;
    int b = blockIdx.z;

    int row_in_warp = lane >> 3;        // 0..3
    int col8 = lane & 7;                // 0..7
    int v = blockIdx.y * TILE_H + warp * 4 + row_in_warp;
    int u0 = blockIdx.x * TILE_W + col8 * 2;

    int pix0 = b * HW + v * WW + u0;

    // Pre-sync phase: depth load (depends only on harness input)
    float2 dv = __ldg((const float2*)&depth[pix0]);

#if __CUDA_ARCH__ >= 900
    cudaGridDependencySynchronize();    // pad grid (incl. g_M pose write) done
#endif

    const float* M = g_M[b];
    float n00 = M[0], n01 = M[1], n02 = M[2];
    float n10 = M[3], n11 = M[4], n12 = M[5];
    float n20 = M[6], n21 = M[7], n22 = M[8];
    float t0  = M[9], t1  = M[10], t2 = M[11];

    float vf = (float)v;
    float rx_ = fmaf(n01, vf, n02);
    float ry_ = fmaf(n11, vf, n12);
    float rz_ = fmaf(n21, vf, n22);

    const uint2* pb_ = &g_pad[(size_t)b * HW];

    int ia0[2], ia1[2], ib0[2], ib1[2];
    float wA[2], wB[2], wC[2], wD[2];

    #pragma unroll
    for (int j = 0; j < 2; j++) {
        float d = (j == 0) ? dv.x : dv.y;
        float uf = (float)(u0 + j);
        float px = fmaf(d, fmaf(n00, uf, rx_), t0);
        float py = fmaf(d, fmaf(n10, uf, ry_), t1);
        float pz = fmaf(d, fmaf(n20, uf, rz_), t2);
        float inv_z = 1.0f / (pz + 1e-10f);
        float xs = px * inv_z;
        float ys = py * inv_z;

        float x0f = floorf(xs), y0f = floorf(ys);
        float fx = xs - x0f, fy = ys - y0f;
        float gx = 1.0f - fx, gy = 1.0f - fy;
        wA[j] = gx * gy;
        wB[j] = gx * fy;
        wC[j] = fx * gy;
        wD[j] = fx * fy;

        int x0 = (int)fminf(fmaxf(x0f, 0.0f), (float)(WW - 1));
        int x1 = (int)fminf(fmaxf(x0f + 1.0f, 0.0f), (float)(WW - 1));
        int y0 = (int)fminf(fmaxf(y0f, 0.0f), (float)(HH - 1));
        int y1 = (int)fminf(fmaxf(y0f + 1.0f, 0.0f), (float)(HH - 1));

        ia0[j] = y0 * WW + x0;
        ia1[j] = y0 * WW + x1;
        ib0[j] = y1 * WW + x0;
        ib1[j] = y1 * WW + x1;
    }

    // All 8 tap loads back-to-back for MLP
    uint2 A0 = __ldg(&pb_[ia0[0]]);
    uint2 C0 = __ldg(&pb_[ia1[0]]);
    uint2 B0 = __ldg(&pb_[ib0[0]]);
    uint2 D0 = __ldg(&pb_[ib1[0]]);
    uint2 A1 = __ldg(&pb_[ia0[1]]);
    uint2 C1 = __ldg(&pb_[ia1[1]]);
    uint2 B1 = __ldg(&pb_[ib0[1]]);
    uint2 D1 = __ldg(&pb_[ib1[1]]);

    float o[6];
    {
        float2 a01 = unpack2(A0.x), a2 = unpack2(A0.y);
        float2 b01 = unpack2(B0.x), b2 = unpack2(B0.y);
        float2 c01 = unpack2(C0.x), c2 = unpack2(C0.y);
        float2 d01 = unpack2(D0.x), d2 = unpack2(D0.y);
        o[0] = fmaf(wA[0], a01.x, fmaf(wB[0], b01.x, fmaf(wC[0], c01.x, wD[0] * d01.x)));
        o[1] = fmaf(wA[0], a01.y, fmaf(wB[0], b01.y, fmaf(wC[0], c01.y, wD[0] * d01.y)));
        o[2] = fmaf(wA[0], a2.x,  fmaf(wB[0], b2.x,  fmaf(wC[0], c2.x,  wD[0] * d2.x)));
    }
    {
        float2 a01 = unpack2(A1.x), a2 = unpack2(A1.y);
        float2 b01 = unpack2(B1.x), b2 = unpack2(B1.y);
        float2 c01 = unpack2(C1.x), c2 = unpack2(C1.y);
        float2 d01 = unpack2(D1.x), d2 = unpack2(D1.y);
        o[3] = fmaf(wA[1], a01.x, fmaf(wB[1], b01.x, fmaf(wC[1], c01.x, wD[1] * d01.x)));
        o[4] = fmaf(wA[1], a01.y, fmaf(wB[1], b01.y, fmaf(wC[1], c01.y, wD[1] * d01.y)));
        o[5] = fmaf(wA[1], a2.x,  fmaf(wB[1], b2.x,  fmaf(wC[1], c2.x,  wD[1] * d2.x)));
    }

    float2* ov = (float2*)(out + (size_t)pix0 * CC);
    ov[0] = make_float2(o[0], o[1]);
    ov[1] = make_float2(o[2], o[3]);
    ov[2] = make_float2(o[4], o[5]);
}

extern "C" void kernel_launch(void* const* d_in, const int* in_sizes, int n_in,
                              void* d_out, int out_size) {
    const float* src   = (const float*)d_in[0];   // [B,H,W,C]
    const float* depth = (const float*)d_in[1];   // [B,H,W]
    const float* pose  = (const float*)d_in[2];   // [B,6]
    const float* K     = (const float*)d_in[3];   // [3,3]
    float* out = (float*)d_out;

    const int threads = 256;

    int pad_blocks = (NQUAD + threads - 1) / threads;      // 3072
    pad_pose_kernel<<<pad_blocks, threads>>>(src, pose, K);

    // Gather with Programmatic Dependent Launch on the pad kernel
    cudaLaunchConfig_t cfg = {};
    cfg.gridDim = dim3(WW / TILE_W, HH / TILE_H, BB);      // 32 x 12 x 16
    cfg.blockDim = dim3(threads, 1, 1);
    cfg.dynamicSmemBytes = 0;
    cfg.stream = 0;
    cudaLaunchAttribute attrs[1];
    attrs[0].id = cudaLaunchAttributeProgrammaticStreamSerialization;
    attrs[0].val.programmaticStreamSerializationAllowed = 1;
    cfg.attrs = attrs;
    cfg.numAttrs = 1;
    cudaLaunchKernelEx(&cfg, warp_kernel, depth, out);
}

// round 16
// speedup vs baseline: 1.2062x; 1.0082x over previous
#include <cuda_runtime.h>
#include <cuda_fp16.h>
#include <math.h>

// Problem constants
#define BB 16
#define HH 384
#define WW 512
#define CC 3
#define HW (HH * WW)
#define NPIX (BB * HW)
#define NQUAD (NPIX / 4)

// Gather tiling: warp covers 16 wide x 4 tall; block = 8 warps = 16 x 32
#define TILE_W 16
#define TILE_H 32

// Per-batch precomputed transform: p = d * (N @ [u,v,1]) + T
__device__ float g_M[BB][12];
// fp16-padded source image: [B,H,W] x (half c0,c1,c2,pad) = 8B/pixel, 25.2MB
__device__ uint2 g_pad[NPIX];

// Packed f32x2 -> half2 conversion: single F2FP.PACK instruction
__device__ __forceinline__ unsigned pack2(float a, float b) {
    __half2 h = __floats2half2_rn(a, b);
    return *reinterpret_cast<unsigned*>(&h);
}
__device__ __forceinline__ uint2 pack_px(float c0, float c1, float c2) {
    uint2 r;
    r.x = pack2(c0, c1);
    r.y = pack2(c2, 0.0f);
    return r;
}
__device__ __forceinline__ float2 unpack2(unsigned w) {
    __half2 h = *reinterpret_cast<const __half2*>(&w);
    return __half22float2(h);
}

// ---------------------------------------------------------------------------
// Kernel 1: pad source to fp16 layout (1 quad/thread — measured best shape);
// block 0 also computes pose matrices into g_M. PDL trigger after all stores.
// ---------------------------------------------------------------------------
__global__ void __launch_bounds__(256) pad_pose_kernel(
    const float* __restrict__ src,
    const float* __restrict__ pose,
    const float* __restrict__ K)
{
    int t = blockIdx.x * blockDim.x + threadIdx.x;

    if (t < NQUAD) {
        const float4* s = (const float4*)src;
        float4 f0 = __ldcs(&s[3 * t + 0]);
        float4 f1 = __ldcs(&s[3 * t + 1]);
        float4 f2 = __ldcs(&s[3 * t + 2]);
        uint2 p0 = pack_px(f0.x, f0.y, f0.z);
        uint2 p1 = pack_px(f0.w, f1.x, f1.y);
        uint2 p2 = pack_px(f1.z, f1.w, f2.x);
        uint2 p3 = pack_px(f2.y, f2.z, f2.w);
        uint4* dst = (uint4*)&g_pad[4 * t];
        dst[0] = make_uint4(p0.x, p0.y, p1.x, p1.y);
        dst[1] = make_uint4(p2.x, p2.y, p3.x, p3.y);
    }

    if (blockIdx.x == 0 && threadIdx.x < BB) {
        int b = threadIdx.x;

        float tx = pose[b * 6 + 0] * 0.01f;
        float ty = pose[b * 6 + 1] * 0.01f;
        float tz = pose[b * 6 + 2] * 0.01f;
        float rx = pose[b * 6 + 3] * 0.001f;
        float ry = pose[b * 6 + 4] * 0.001f;
        float rz = pose[b * 6 + 5] * 0.001f;

        float cx = cosf(rx), sx = sinf(rx);
        float cy = cosf(ry), sy = sinf(ry);
        float cz = cosf(rz), sz = sinf(rz);

        // R = Rz @ Ry @ Rx
        float Rzy[9];
        Rzy[0] = cz * cy;  Rzy[1] = -sz;  Rzy[2] = cz * sy;
        Rzy[3] = sz * cy;  Rzy[4] = cz;   Rzy[5] = sz * sy;
        Rzy[6] = -sy;      Rzy[7] = 0.f;  Rzy[8] = cy;
        float R[9];
        R[0] = Rzy[0];
        R[1] = Rzy[1] * cx + Rzy[2] * sx;
        R[2] = -Rzy[1] * sx + Rzy[2] * cx;
        R[3] = Rzy[3];
        R[4] = Rzy[4] * cx + Rzy[5] * sx;
        R[5] = -Rzy[4] * sx + Rzy[5] * cx;
        R[6] = Rzy[6];
        R[7] = Rzy[7] * cx + Rzy[8] * sx;
        R[8] = -Rzy[7] * sx + Rzy[8] * cx;

        float k00 = K[0], k01 = K[1], k02 = K[2];
        float k10 = K[3], k11 = K[4], k12 = K[5];
        float k20 = K[6], k21 = K[7], k22 = K[8];

        float c00 = k11 * k22 - k12 * k21;
        float c01 = k12 * k20 - k10 * k22;
        float c02 = k10 * k21 - k11 * k20;
        float det = k00 * c00 + k01 * c01 + k02 * c02;
        float id = 1.0f / det;
        float Ki[9];
        Ki[0] = c00 * id;
        Ki[1] = (k02 * k21 - k01 * k22) * id;
        Ki[2] = (k01 * k12 - k02 * k11) * id;
        Ki[3] = c01 * id;
        Ki[4] = (k00 * k22 - k02 * k20) * id;
        Ki[5] = (k02 * k10 - k00 * k12) * id;
        Ki[6] = c02 * id;
        Ki[7] = (k01 * k20 - k00 * k21) * id;
        Ki[8] = (k00 * k11 - k01 * k10) * id;

        float M33[9], Mt[3];
        #pragma unroll
        for (int i = 0; i < 3; i++) {
            float a0 = (i == 0) ? k00 : (i == 1) ? k10 : k20;
            float a1 = (i == 0) ? k01 : (i == 1) ? k11 : k21;
            float a2 = (i == 0) ? k02 : (i == 1) ? k12 : k22;
            #pragma unroll
            for (int j = 0; j < 3; j++)
                M33[i * 3 + j] = a0 * R[j] + a1 * R[3 + j] + a2 * R[6 + j];
            Mt[i] = a0 * tx + a1 * ty + a2 * tz;
        }

        #pragma unroll
        for (int i = 0; i < 3; i++) {
            #pragma unroll
            for (int j = 0; j < 3; j++) {
                g_M[b][i * 3 + j] = M33[i * 3 + 0] * Ki[j]
                                  + M33[i * 3 + 1] * Ki[3 + j]
                                  + M33[i * 3 + 2] * Ki[6 + j];
            }
            g_M[b][9 + i] = Mt[i];
        }
    }

#if __CUDA_ARCH__ >= 900
    cudaTriggerProgrammaticLaunchCompletion();
#endif
}

// ---------------------------------------------------------------------------
// Kernel 2: warp + bilinear gather. 2 px/thread, 2-D warp tiles (16x4).
// PDL: only the depth load (input-only) runs before the grid sync;
// g_M read + projection + taps after (g_M is pad-grid-written).
// ---------------------------------------------------------------------------
__global__ void __launch_bounds__(256) warp_kernel(
    const float* __restrict__ depth,
    float* __restrict__ out)
{
    int lane = threadIdx.x & 31;
    int warp = threadIdx.x >> 5;
    int b = blockIdx.z;

    int row_in_warp = lane >> 3;        // 0..3
    int col8 = lane & 7;                // 0..7
    int v = blockIdx.y * TILE_H + warp * 4 + row_in_warp;
    int u0 = blockIdx.x * TILE_W + col8 * 2;

    int pix0 = b * HW + v * WW + u0;

    // Pre-sync phase: depth load (depends only on harness input)
    float2 dv = __ldg((const float2*)&depth[pix0]);

#if __CUDA_ARCH__ >= 900
    cudaGridDependencySynchronize();    // pad grid (incl. g_M pose write) done
#endif

    const float* M = g_M[b];
    float n00 = M[0], n01 = M[1], n02 = M[2];
    float n10 = M[3], n11 = M[4], n12 = M[5];
    float n20 = M[6], n21 = M[7], n22 = M[8];
    float t0  = M[9], t1  = M[10], t2 = M[11];

    float vf = (float)v;
    float rx_ = fmaf(n01, vf, n02);
    float ry_ = fmaf(n11, vf, n12);
    float rz_ = fmaf(n21, vf, n22);

    const uint2* pb_ = &g_pad[(size_t)b * HW];

    int ia0[2], ia1[2], ib0[2], ib1[2];
    float wA[2], wB[2], wC[2], wD[2];

    #pragma unroll
    for (int j = 0; j < 2; j++) {
        float d = (j == 0) ? dv.x : dv.y;
        float uf = (float)(u0 + j);
        float px = fmaf(d, fmaf(n00, uf, rx_), t0);
        float py = fmaf(d, fmaf(n10, uf, ry_), t1);
        float pz = fmaf(d, fmaf(n20, uf, rz_), t2);
        float inv_z = 1.0f / (pz + 1e-10f);
        float xs = px * inv_z;
        float ys = py * inv_z;

        float x0f = floorf(xs), y0f = floorf(ys);
        float fx = xs - x0f, fy = ys - y0f;
        float gx = 1.0f - fx, gy = 1.0f - fy;
        wA[j] = gx * gy;
        wB[j] = gx * fy;
        wC[j] = fx * gy;
        wD[j] = fx * fy;

        int x0 = (int)fminf(fmaxf(x0f, 0.0f), (float)(WW - 1));
        int x1 = (int)fminf(fmaxf(x0f + 1.0f, 0.0f), (float)(WW - 1));
        int y0 = (int)fminf(fmaxf(y0f, 0.0f), (float)(HH - 1));
        int y1 = (int)fminf(fmaxf(y0f + 1.0f, 0.0f), (float)(HH - 1));

        ia0[j] = y0 * WW + x0;
        ia1[j] = y0 * WW + x1;
        ib0[j] = y1 * WW + x0;
        ib1[j] = y1 * WW + x1;
    }

    // All 8 tap loads back-to-back for MLP
    uint2 A0 = __ldg(&pb_[ia0[0]]);
    uint2 C0 = __ldg(&pb_[ia1[0]]);
    uint2 B0 = __ldg(&pb_[ib0[0]]);
    uint2 D0 = __ldg(&pb_[ib1[0]]);
    uint2 A1 = __ldg(&pb_[ia0[1]]);
    uint2 C1 = __ldg(&pb_[ia1[1]]);
    uint2 B1 = __ldg(&pb_[ib0[1]]);
    uint2 D1 = __ldg(&pb_[ib1[1]]);

    float o[6];
    {
        float2 a01 = unpack2(A0.x), a2 = unpack2(A0.y);
        float2 b01 = unpack2(B0.x), b2 = unpack2(B0.y);
        float2 c01 = unpack2(C0.x), c2 = unpack2(C0.y);
        float2 d01 = unpack2(D0.x), d2 = unpack2(D0.y);
        o[0] = fmaf(wA[0], a01.x, fmaf(wB[0], b01.x, fmaf(wC[0], c01.x, wD[0] * d01.x)));
        o[1] = fmaf(wA[0], a01.y, fmaf(wB[0], b01.y, fmaf(wC[0], c01.y, wD[0] * d01.y)));
        o[2] = fmaf(wA[0], a2.x,  fmaf(wB[0], b2.x,  fmaf(wC[0], c2.x,  wD[0] * d2.x)));
    }
    {
        float2 a01 = unpack2(A1.x), a2 = unpack2(A1.y);
        float2 b01 = unpack2(B1.x), b2 = unpack2(B1.y);
        float2 c01 = unpack2(C1.x), c2 = unpack2(C1.y);
        float2 d01 = unpack2(D1.x), d2 = unpack2(D1.y);
        o[3] = fmaf(wA[1], a01.x, fmaf(wB[1], b01.x, fmaf(wC[1], c01.x, wD[1] * d01.x)));
        o[4] = fmaf(wA[1], a01.y, fmaf(wB[1], b01.y, fmaf(wC[1], c01.y, wD[1] * d01.y)));
        o[5] = fmaf(wA[1], a2.x,  fmaf(wB[1], b2.x,  fmaf(wC[1], c2.x,  wD[1] * d2.x)));
    }

    float2* ov = (float2*)(out + (size_t)pix0 * CC);
    ov[0] = make_float2(o[0], o[1]);
    ov[1] = make_float2(o[2], o[3]);
    ov[2] = make_float2(o[4], o[5]);
}

extern "C" void kernel_launch(void* const* d_in, const int* in_sizes, int n_in,
                              void* d_out, int out_size) {
    const float* src   = (const float*)d_in[0];   // [B,H,W,C]
    const float* depth = (const float*)d_in[1];   // [B,H,W]
    const float* pose  = (const float*)d_in[2];   // [B,6]
    const float* K     = (const float*)d_in[3];   // [3,3]
    float* out = (float*)d_out;

    const int threads = 256;

    int pad_blocks = (NQUAD + threads - 1) / threads;      // 3072
    pad_pose_kernel<<<pad_blocks, threads>>>(src, pose, K);

    // Gather with Programmatic Dependent Launch on the pad kernel
    cudaLaunchConfig_t cfg = {};
    cfg.gridDim = dim3(WW / TILE_W, HH / TILE_H, BB);      // 32 x 12 x 16
    cfg.blockDim = dim3(threads, 1, 1);
    cfg.dynamicSmemBytes = 0;
    cfg.stream = 0;
    cudaLaunchAttribute attrs[1];
    attrs[0].id = cudaLaunchAttributeProgrammaticStreamSerialization;
    attrs[0].val.programmaticStreamSerializationAllowed = 1;
    cfg.attrs = attrs;
    cfg.numAttrs = 1;
    cudaLaunchKernelEx(&cfg, warp_kernel, depth, out);
}